// round 7
// baseline (speedup 1.0000x reference)
#include <cuda_runtime.h>
#include <cstdint>

// ---------------------------------------------------------------------------
// HT model via split-tf32 mma.sync, cp.async double-buffered pipeline.
// Pairwise tree products are hoisted into tiny HBM-bound elementwise kernels,
// so every GEMM is the same plain kernel:
//   C[j][m,n] = act( sum_k A[j][m,k] * W[j][n,k or k,n] + bias[n] )
// smem: pad-20 linear layout (80B row stride) -> conflict-free cp.async
// stores AND fragment LDS with compile-time immediate offsets (no index ALU).
// tf32 split x = hi + lo in registers; 3 MMAs (hi*hi + hi*lo + lo*hi) per
// m16n8k8 product into fp32 accumulators (~2^-21 error/GEMM, budget 1e-3).
// CTA tile 128x64, BK=16, 8 warps (4x2), warp tile 32x32.
// ---------------------------------------------------------------------------

__device__ float g_h1[262144L * 128];
__device__ float g_bufA[262144L * 64];
__device__ float g_bufB[262144L * 64];

#define STG_FLOATS 3840          // A 128*20=2560 | B 64*20=1280
#define DYN_SMEM (2 * STG_FLOATS * 4)   // 30720 B < 48 KB

static __device__ __forceinline__ uint32_t smem_u32(const void* p) {
    uint32_t a;
    asm("{ .reg .u64 t; cvta.to.shared.u64 t, %1; cvt.u32.u64 %0, t; }" : "=r"(a) : "l"(p));
    return a;
}
static __device__ __forceinline__ void cp16(uint32_t dst, const void* src) {
    asm volatile("cp.async.ca.shared.global [%0], [%1], 16;" :: "r"(dst), "l"(src));
}
static __device__ __forceinline__ void cp4(uint32_t dst, const void* src) {
    asm volatile("cp.async.ca.shared.global [%0], [%1], 4;" :: "r"(dst), "l"(src));
}
#define CP_COMMIT() asm volatile("cp.async.commit_group;" ::: "memory")
#define CP_WAIT1()  asm volatile("cp.async.wait_group 1;" ::: "memory")

static __device__ __forceinline__ float tf32_hi(float x) {
    uint32_t h;
    asm("cvt.rna.tf32.f32 %0, %1;" : "=r"(h) : "f"(x));
    return __uint_as_float(h);
}

#define MMA_TF32(d, a, b)                                                     \
    asm volatile(                                                             \
        "mma.sync.aligned.m16n8k8.row.col.f32.tf32.tf32.f32 "                 \
        "{%0,%1,%2,%3}, {%4,%5,%6,%7}, {%8,%9}, {%0,%1,%2,%3};"               \
        : "+f"((d)[0]), "+f"((d)[1]), "+f"((d)[2]), "+f"((d)[3])              \
        : "r"((a)[0]), "r"((a)[1]), "r"((a)[2]), "r"((a)[3]),                 \
          "r"((b)[0]), "r"((b)[1]))

template <int KDIM, bool WT, bool RELU>
__global__ void __launch_bounds__(256, 3) mma_gemm(
    const float* __restrict__ A1base, long ldA, long jStrideA,
    const float* __restrict__ Wbase, long jStrideW,
    const float* __restrict__ bias,
    float* __restrict__ Cbase, long ldC, long jStrideC,
    int Ndim)
{
    extern __shared__ float sm[];
    constexpr int NST = KDIM / 16;

    const int j = blockIdx.z;
    const float* A1 = A1base + (long)j * jStrideA;
    const float* W  = Wbase  + (long)j * jStrideW;
    float* C        = Cbase  + (long)j * jStrideC;
    const int m0 = blockIdx.x * 128;
    const int n0 = blockIdx.y * 64;

    const int tid = threadIdx.x;
    const int wid = tid >> 5, lid = tid & 31;
    const int wm = wid >> 1, wn = wid & 1;     // warps: 4 along M x 2 along N
    const int g = lid >> 2, tig = lid & 3;

    const uint32_t smb = smem_u32(sm);

    // ---- per-thread source pointers (advanced by 16 floats per stage) ----
    const int ar = tid & 127;         // A row
    const int ac = tid >> 7;          // A chunk 0/1 (also does ac+2)
    const float* aS = A1 + (long)(m0 + ar) * ldA + ac * 4;
    const uint32_t aD = smb + (uint32_t)(ar * 20 + ac * 4) * 4;

    const float* wS = nullptr;        // WT path
    uint32_t bD = 0;
    const float* wN = nullptr;        // non-WT path
    uint32_t bD4 = 0;
    if (WT) {
        const int brow = tid & 63, bc = tid >> 6;
        int n = n0 + brow; if (n >= Ndim) n = Ndim - 1;
        wS = W + (long)n * KDIM + bc * 4;
        bD = smb + (uint32_t)(2560 + brow * 20 + bc * 4) * 4;
    } else {
        const int brow = tid >> 2, k0 = (tid & 3) * 4;
        int n = n0 + brow; if (n >= Ndim) n = Ndim - 1;
        wN = W + (long)k0 * Ndim + n;
        bD4 = smb + (uint32_t)(2560 + brow * 20 + k0) * 4;
    }

    auto issue = [&](int buf) {
        const uint32_t off = (uint32_t)buf * (STG_FLOATS * 4);
        cp16(aD + off, aS);
        cp16(aD + off + 32, aS + 8);
        aS += 16;
        if (WT) {
            cp16(bD + off, wS);
            wS += 16;
        } else {
#pragma unroll
            for (int i = 0; i < 4; i++)
                cp4(bD4 + off + i * 4, wN + (long)i * (long)Ndim);
            wN += 16 * (long)Ndim;
        }
    };

    float d[2][4][4];
#pragma unroll
    for (int mt = 0; mt < 2; mt++)
#pragma unroll
        for (int nt = 0; nt < 4; nt++)
#pragma unroll
            for (int q = 0; q < 4; q++) d[mt][nt][q] = 0.f;

    const float* Ap0 = sm + (wm * 32 + g) * 20 + tig;
    const float* Bp0 = sm + 2560 + (wn * 32 + g) * 20 + tig;

    auto compute = [&](int buf) {
        const float* Ap = Ap0 + buf * STG_FLOATS;
        const float* Bp = Bp0 + buf * STG_FLOATS;
#pragma unroll
        for (int kc = 0; kc < 2; kc++) {
            uint32_t ah[2][4], al[2][4], bh[4][2], bl[4][2];
#pragma unroll
            for (int mt = 0; mt < 2; mt++)
#pragma unroll
                for (int i = 0; i < 4; i++) {
                    const float v = Ap[(mt * 16 + (i & 1) * 8) * 20 + kc * 8 + (i >> 1) * 4];
                    const float hi = tf32_hi(v);
                    ah[mt][i] = __float_as_uint(hi);
                    al[mt][i] = __float_as_uint(v - hi);
                }
#pragma unroll
            for (int nt = 0; nt < 4; nt++)
#pragma unroll
                for (int i = 0; i < 2; i++) {
                    const float v = Bp[(nt * 8) * 20 + kc * 8 + i * 4];
                    const float hi = tf32_hi(v);
                    bh[nt][i] = __float_as_uint(hi);
                    bl[nt][i] = __float_as_uint(v - hi);
                }
#pragma unroll
            for (int mt = 0; mt < 2; mt++)
#pragma unroll
                for (int nt = 0; nt < 4; nt++) {
                    MMA_TF32(d[mt][nt], ah[mt], bh[nt]);
                    MMA_TF32(d[mt][nt], ah[mt], bl[nt]);
                    MMA_TF32(d[mt][nt], al[mt], bh[nt]);
                }
        }
    };

    // ---- pipeline: 2 cp.async stages in flight ----
    issue(0);
    CP_COMMIT();
    issue(1);
    CP_COMMIT();

    for (int s = 0; s < NST; s++) {
        CP_WAIT1();
        __syncthreads();
        compute(s & 1);
        __syncthreads();
        if (s + 2 < NST) issue(s & 1);
        CP_COMMIT();
    }

    // ---- epilogue (float2 stores; all Ndim/ldC are even) ----
#pragma unroll
    for (int mt = 0; mt < 2; mt++) {
        const int r0 = m0 + wm * 32 + mt * 16 + g;
#pragma unroll
        for (int nt = 0; nt < 4; nt++) {
            const int c = n0 + wn * 32 + nt * 8 + 2 * tig;
            if (c + 1 < Ndim) {
#pragma unroll
                for (int half = 0; half < 2; half++) {
                    const long row = r0 + half * 8;
                    float v0 = d[mt][nt][half * 2 + 0];
                    float v1 = d[mt][nt][half * 2 + 1];
                    if (bias) {
                        v0 += __ldg(&bias[c]);
                        v1 += __ldg(&bias[c + 1]);
                    }
                    if (RELU) { v0 = fmaxf(v0, 0.f); v1 = fmaxf(v1, 0.f); }
                    *(float2*)(C + row * ldC + c) = make_float2(v0, v1);
                }
            }
        }
    }
}

// prod[e] = t[2e - (e & (rq-1))] * t[2e - (e & (rq-1)) + rq]   (float4 units)
__global__ void __launch_bounds__(256) pairprod(
    const float4* __restrict__ t, float4* __restrict__ p, int rqm1, long total4)
{
    const long e = (long)blockIdx.x * 256 + threadIdx.x;
    if (e >= total4) return;
    const long t0 = 2 * e - (e & rqm1);
    const float4 u = t[t0];
    const float4 v = t[t0 + rqm1 + 1];
    p[e] = make_float4(u.x * v.x, u.y * v.y, u.z * v.z, u.w * v.w);
}

extern "C" void kernel_launch(void* const* d_in, const int* in_sizes, int n_in,
                              void* d_out, int out_size)
{
    const float* X    = (const float*)d_in[0];   // (4096,64,64)
    const float* W1   = (const float*)d_in[1];   // (64,128)
    const float* b1   = (const float*)d_in[2];
    const float* W2   = (const float*)d_in[3];   // (128,64)
    const float* b2   = (const float*)d_in[4];
    const float* W3   = (const float*)d_in[5];   // (64,32)
    const float* b3   = (const float*)d_in[6];
    const float* W4   = (const float*)d_in[7];   // (32,32)
    const float* b4   = (const float*)d_in[8];
    const float* P0   = (const float*)d_in[9];   // (64,64,32)
    const float* P1   = (const float*)d_in[10];  // (32,128,64)
    const float* P2   = (const float*)d_in[11];  // (16,256,128)
    const float* P3   = (const float*)d_in[12];  // (8,512,256)
    const float* P4   = (const float*)d_in[13];  // (4,512,512)
    const float* P5   = (const float*)d_in[14];  // (2,512,512)
    const float* Ptop = (const float*)d_in[15];  // (1000,512)
    float* out = (float*)d_out;                  // (4096,1000)

    float *h1, *bufA, *bufB;
    cudaGetSymbolAddress((void**)&h1,  g_h1);
    cudaGetSymbolAddress((void**)&bufA, g_bufA);
    cudaGetSymbolAddress((void**)&bufB, g_bufB);

    const dim3 blk(256);

    // ---- MLP over 262144 rows ----
    mma_gemm<64, false, true><<<dim3(2048, 2, 1), blk, DYN_SMEM>>>(
        X, 64, 0, W1, 0, b1, h1, 128, 0, 128);
    mma_gemm<128, false, true><<<dim3(2048, 1, 1), blk, DYN_SMEM>>>(
        h1, 128, 0, W2, 0, b2, bufA, 64, 0, 64);
    mma_gemm<64, false, true><<<dim3(2048, 1, 1), blk, DYN_SMEM>>>(
        bufA, 64, 0, W3, 0, b3, h1, 32, 0, 32);
    mma_gemm<32, false, false><<<dim3(2048, 1, 1), blk, DYN_SMEM>>>(
        h1, 32, 0, W4, 0, b4, bufB, 32, 0, 32);

    // ---- Leaf: t0[b,j,a] = sum_m P0[j,a,m]*F[b,j,m] -> bufA (B,64,64) ----
    mma_gemm<32, true, false><<<dim3(32, 1, 64), blk, DYN_SMEM>>>(
        bufB, 2048, 32, P0, 2048, nullptr, bufA, 4096, 64, 64);

    // ---- Tree: pairprod -> GEMM per level ----
    // L1: bufA (B,64,64) -> prod h1 (B,32,64) -> bufB (B,32,128)
    pairprod<<<8192, blk>>>((const float4*)bufA, (float4*)h1, 15, 2097152);
    mma_gemm<64, true, false><<<dim3(32, 2, 32), blk, DYN_SMEM>>>(
        h1, 2048, 64, P1, 128L * 64, nullptr, bufB, 4096, 128, 128);
    // L2: bufB (B,32,128) -> prod h1 (B,16,128) -> bufA (B,16,256)
    pairprod<<<8192, blk>>>((const float4*)bufB, (float4*)h1, 31, 2097152);
    mma_gemm<128, true, false><<<dim3(32, 4, 16), blk, DYN_SMEM>>>(
        h1, 2048, 128, P2, 256L * 128, nullptr, bufA, 4096, 256, 256);
    // L3: bufA (B,16,256) -> prod h1 (B,8,256) -> bufB (B,8,512)
    pairprod<<<8192, blk>>>((const float4*)bufA, (float4*)h1, 63, 2097152);
    mma_gemm<256, true, false><<<dim3(32, 8, 8), blk, DYN_SMEM>>>(
        h1, 2048, 256, P3, 512L * 256, nullptr, bufB, 4096, 512, 512);
    // L4: bufB (B,8,512) -> prod h1 (B,4,512) -> bufA (B,4,512)
    pairprod<<<8192, blk>>>((const float4*)bufB, (float4*)h1, 127, 2097152);
    mma_gemm<512, true, false><<<dim3(32, 8, 4), blk, DYN_SMEM>>>(
        h1, 2048, 512, P4, 512L * 512, nullptr, bufA, 2048, 512, 512);
    // L5: bufA (B,4,512) -> prod h1 (B,2,512) -> bufB (B,2,512)
    pairprod<<<4096, blk>>>((const float4*)bufA, (float4*)h1, 127, 1048576);
    mma_gemm<512, true, false><<<dim3(32, 8, 2), blk, DYN_SMEM>>>(
        h1, 1024, 512, P5, 512L * 512, nullptr, bufB, 1024, 512, 512);
    // Top: bufB (B,2,512) -> prod h1 (B,1,512) -> out (B,1000)
    pairprod<<<2048, blk>>>((const float4*)bufB, (float4*)h1, 127, 524288);
    mma_gemm<512, true, false><<<dim3(32, 16, 1), blk, DYN_SMEM>>>(
        h1, 512, 0, Ptop, 0, nullptr, out, 1000, 0, 1000);
}